// round 15
// baseline (speedup 1.0000x reference)
#include <cuda_runtime.h>
#include <cuda_bf16.h>
#include <cstdint>

// ---------------------------------------------------------------------------
// C[16384,768](fp32) = A[16384,6144] @ W[768,6144]^T
//
// Inputs are FP32 (bf16 values upcast by the harness -> lossless to re-pack).
//   1) tiny convert: W fp32 -> bf16 scratch (9.4 MB, ~7us)
//   2) GEMM: A fragments loaded DIRECTLY from fp32 gmem (float2 -> bf16x2
//      pack; replicates the validated ldmatrix fragment order). B via
//      cp.async + SW128 smem + ldmatrix (3-stage). mma.sync m16n8k16 bf16.
//      CTA tile 128x256, 512 threads = 4(M)x4(N) warps, warp tile 32x64.
//      No A convert kernel, no A smem: deletes ~97us of pure overhead.
// ---------------------------------------------------------------------------

#define HIDDEN 6144
#define NTOK   16384
#define NEXP   768

#define TM 128
#define TN 256
#define KC 64
#define KT (HIDDEN / KC)          // 96
#define STAGES 3
#define THREADS 512

#define ROWB (HIDDEN * 2)         // bf16 W-scratch row stride (bytes)

#define B_BYTES (TN * 128)        // 32 KB per stage (B only)
#define SMEM_TOTAL (STAGES * B_BYTES)   // 98304 B

// Static scratch (allocation-free): bf16 copy of W only.
__device__ __nv_bfloat16 g_Wbf[(size_t)NEXP * HIDDEN];   // ~9.4 MB

#define NW4 ((NEXP * HIDDEN) / 4)     // 1179648 float4 chunks in W

// -------- W fp32 -> bf16 conversion (lossless) -----------------------------
__global__ void __launch_bounds__(256)
convert_w_kernel(const float* __restrict__ srcW) {
    int i = blockIdx.x * blockDim.x + threadIdx.x;
    if (i < NW4) {
        float4 v = reinterpret_cast<const float4*>(srcW)[i];
        __nv_bfloat162 lo = __floats2bfloat162_rn(v.x, v.y);
        __nv_bfloat162 hi = __floats2bfloat162_rn(v.z, v.w);
        reinterpret_cast<__nv_bfloat162*>(g_Wbf)[2 * i]     = lo;
        reinterpret_cast<__nv_bfloat162*>(g_Wbf)[2 * i + 1] = hi;
    }
}

// ------------------------------- GEMM --------------------------------------
__device__ __forceinline__ uint32_t s2u(const void* p) {
    return (uint32_t)__cvta_generic_to_shared(p);
}

__device__ __forceinline__ void cp16(uint32_t s, const void* g) {
    asm volatile("cp.async.cg.shared.global [%0], [%1], 16;" :: "r"(s), "l"(g));
}

__device__ __forceinline__ uint32_t sw128(uint32_t o) {
    return o ^ ((o >> 3) & 0x70);
}

__device__ __forceinline__ void ldsm_x4(uint32_t& r0, uint32_t& r1,
                                        uint32_t& r2, uint32_t& r3, uint32_t addr) {
    asm volatile("ldmatrix.sync.aligned.m8n8.x4.shared.b16 {%0,%1,%2,%3}, [%4];"
                 : "=r"(r0), "=r"(r1), "=r"(r2), "=r"(r3) : "r"(addr));
}

__device__ __forceinline__ void mma16816(float* d, const uint32_t* a, const uint32_t* b) {
    asm volatile(
        "mma.sync.aligned.m16n8k16.row.col.f32.bf16.bf16.f32 "
        "{%0,%1,%2,%3}, {%4,%5,%6,%7}, {%8,%9}, {%0,%1,%2,%3};"
        : "+f"(d[0]), "+f"(d[1]), "+f"(d[2]), "+f"(d[3])
        : "r"(a[0]), "r"(a[1]), "r"(a[2]), "r"(a[3]), "r"(b[0]), "r"(b[1]));
}

__device__ __forceinline__ uint32_t packbf(float2 v) {
    __nv_bfloat162 h = __floats2bfloat162_rn(v.x, v.y);   // x -> low half
    return *reinterpret_cast<uint32_t*>(&h);
}

// Load one B stage: TN x KC, K-major 128B rows, SW128-swizzled cp.async.
__device__ __forceinline__ void load_stage_b(const char* gB, uint32_t sB, int tid) {
    #pragma unroll
    for (int i = 0; i < (B_BYTES / 16) / THREADS; i++) {      // 4 chunks
        int chunk = tid + i * THREADS;
        int row = chunk >> 3;
        int c = (chunk & 7) * 16;
        cp16(sB + sw128((uint32_t)(row * 128 + c)), gB + (size_t)row * ROWB + c);
    }
}

__global__ void __launch_bounds__(THREADS, 1)
router_gemm_kernel(const float* __restrict__ A, float* __restrict__ C) {
    extern __shared__ char smem[];
    const uint32_t sbase = s2u(smem);
    const int tid = threadIdx.x;
    const int wid = tid >> 5;
    const int lid = tid & 31;

    const int wm = wid & 3;        // warp row (0..3): 32 M-rows each
    const int wn = wid >> 2;       // warp col (0..3): 64 N-cols each

    const int n0 = blockIdx.x * TN;    // n-fast: 3 adjacent CTAs share A in L2
    const int m0 = blockIdx.y * TM;

    const char* gB0 = (const char*)(g_Wbf + (size_t)n0 * HIDDEN);

    // ---- A fragment base pointer (direct fp32 gmem loads) ----
    // Fragment layout (validated): r = lid>>2, c = (lid&3)*2
    //   a0=(r, c)(r, c+1)   a1=(r+8, c)..   a2=(r, c+8)..   a3=(r+8, c+8)..
    const float* aptr = A + (size_t)(m0 + wm * 32 + (lid >> 2)) * HIDDEN
                          + (lid & 3) * 2;

    // ---- B ldmatrix per-thread offsets (within CTA tile, pre-swizzle) ----
    const int b_row = wn * 64 + (lid & 7) + ((lid >> 4) & 1) * 8;  // + ni2*16
    const int b_kb  = ((lid >> 3) & 1) * 16;

    float acc[2][8][4];
    #pragma unroll
    for (int mi = 0; mi < 2; mi++)
        #pragma unroll
        for (int ni = 0; ni < 8; ni++)
            #pragma unroll
            for (int j = 0; j < 4; j++) acc[mi][ni][j] = 0.0f;

    // Prologue: B stages 0..STAGES-2
    #pragma unroll
    for (int s = 0; s < STAGES - 1; s++) {
        load_stage_b(gB0 + s * (KC * 2), sbase + s * B_BYTES, tid);
        asm volatile("cp.async.commit_group;" ::: "memory");
    }

    for (int kt = 0; kt < KT; kt++) {
        asm volatile("cp.async.wait_group %0;" :: "n"(STAGES - 2) : "memory");
        __syncthreads();

        int kl = kt + STAGES - 1;
        if (kl < KT) {
            load_stage_b(gB0 + kl * (KC * 2), sbase + (kl % STAGES) * B_BYTES, tid);
        }
        asm volatile("cp.async.commit_group;" ::: "memory");

        const uint32_t sB = sbase + (kt % STAGES) * B_BYTES;
        const int kbase = kt * KC;

        #pragma unroll
        for (int ks = 0; ks < KC / 16; ks++) {
            const int col = kbase + ks * 16;

            // A fragments straight from gmem (L1-resident tile), fp32->bf16x2.
            uint32_t a[2][4];
            #pragma unroll
            for (int mi = 0; mi < 2; mi++) {
                const float* p = aptr + (size_t)(mi * 16) * HIDDEN + col;
                float2 v0 = *reinterpret_cast<const float2*>(p);
                float2 v1 = *reinterpret_cast<const float2*>(p + 8 * HIDDEN);
                float2 v2 = *reinterpret_cast<const float2*>(p + 8);
                float2 v3 = *reinterpret_cast<const float2*>(p + 8 * HIDDEN + 8);
                a[mi][0] = packbf(v0);
                a[mi][1] = packbf(v1);
                a[mi][2] = packbf(v2);
                a[mi][3] = packbf(v3);
            }

            uint32_t b[8][2];
            #pragma unroll
            for (int ni2 = 0; ni2 < 4; ni2++) {
                uint32_t addr = sB + sw128((uint32_t)((b_row + ni2 * 16) * 128
                                                      + ks * 32 + b_kb));
                ldsm_x4(b[ni2 * 2][0], b[ni2 * 2][1],
                        b[ni2 * 2 + 1][0], b[ni2 * 2 + 1][1], addr);
            }
            #pragma unroll
            for (int mi = 0; mi < 2; mi++)
                #pragma unroll
                for (int ni = 0; ni < 8; ni++)
                    mma16816(acc[mi][ni], a[mi], b[ni]);
        }
    }

    // Epilogue: direct fp32 stores (validated layout).
    {
        const int tr = lid >> 2;          // 0..7
        const int tc = (lid & 3) * 2;     // 0,2,4,6
        #pragma unroll
        for (int mi = 0; mi < 2; mi++) {
            int row_lo = m0 + wm * 32 + mi * 16 + tr;
            float* out_lo = C + (size_t)row_lo * NEXP + n0 + wn * 64 + tc;
            float* out_hi = out_lo + 8 * NEXP;
            #pragma unroll
            for (int ni = 0; ni < 8; ni++) {
                *reinterpret_cast<float2*>(out_lo + ni * 8) =
                    make_float2(acc[mi][ni][0], acc[mi][ni][1]);
                *reinterpret_cast<float2*>(out_hi + ni * 8) =
                    make_float2(acc[mi][ni][2], acc[mi][ni][3]);
            }
        }
    }
}

extern "C" void kernel_launch(void* const* d_in, const int* in_sizes, int n_in,
                              void* d_out, int out_size) {
    // Inputs are FLOAT32 (bf16 values upcast by the harness).
    const int nA = NTOK * HIDDEN;
    const float* Af;
    const float* Wf;
    if (in_sizes[0] == nA) {
        Af = (const float*)d_in[0];
        Wf = (const float*)d_in[1];
    } else {
        Af = (const float*)d_in[1];
        Wf = (const float*)d_in[0];
    }
    float* C = (float*)d_out;

    convert_w_kernel<<<(NW4 + 255) / 256, 256>>>(Wf);

    cudaFuncSetAttribute(router_gemm_kernel,
                         cudaFuncAttributeMaxDynamicSharedMemorySize, SMEM_TOTAL);
    dim3 grid(NEXP / TN, NTOK / TM);   // (3, 128)
    router_gemm_kernel<<<grid, THREADS, SMEM_TOTAL>>>(Af, C);
}

// round 17
// speedup vs baseline: 1.1481x; 1.1481x over previous
#include <cuda_runtime.h>
#include <cuda_bf16.h>
#include <cstdint>

// ---------------------------------------------------------------------------
// C[16384,768](fp32) = A[16384,6144] @ W[768,6144]^T
//
// Inputs are FP32 (bf16 values upcast by the harness -> lossless re-pack).
//   1) tiny convert: W fp32 -> bf16 scratch (9.4 MB, ~7us)
//   2) GEMM with FUSED A-conversion:
//        cp.async stages A as fp32 (linear) + B as bf16 (SW128).
//        Each thread converts the exact 16B chunks it cp.async'd
//        (LDS.128 -> CVT -> STS.64 into SW128 bf16 A tile) BEFORE the
//        barrier (thread-local => legal), then the validated
//        ldmatrix + mma.sync.m16n8k16 consumer runs unchanged.
//   CTA tile 128x256, 512 threads = 4(M)x4(N) warps, warp tile 32x64.
//   Slots: A32 x2 (32KB), Abf x3 (16KB), B x3 (32KB) = 208KB, occ 1.
//
// R16 bug (fixed here): steady-state A loads passed BOTH an advanced base
// pointer AND kbase, doubling the K offset for stages >= 2. Now the base
// pointer is always gA0 and kbase alone selects the stage.
//
// Pipeline per iter kt:
//   1. wait_group 0           -> stage kt+1 (A32+B) arrived
//   2. convert A32[(kt+1)%2] -> Abf[(kt+1)%3]   (thread-local chunks)
//   3. __syncthreads          -> publishes Abf[kt+1], B[kt+1]
//   4. cp.async stage kt+2 -> A32[kt%2], B[(kt+2)%3]; commit
//   5. compute stage kt from Abf[kt%3], B[kt%3]
//   Slot-safety and wait accounting proven in R16 analysis (unchanged).
// ---------------------------------------------------------------------------

#define HIDDEN 6144
#define NTOK   16384
#define NEXP   768

#define TM 128
#define TN 256
#define KC 64
#define KT (HIDDEN / KC)          // 96
#define THREADS 512

#define ROWB (HIDDEN * 2)         // bf16 W-scratch row stride (bytes)

#define A32_BYTES (TM * KC * 4)   // 32768 per stage (fp32 A, linear)
#define ABF_BYTES (TM * 128)      // 16384 per stage (bf16 A, SW128)
#define B_BYTES   (TN * 128)      // 32768 per stage (bf16 B, SW128)

#define A32_OFF 0
#define ABF_OFF (2 * A32_BYTES)               // 65536
#define B_OFF   (ABF_OFF + 3 * ABF_BYTES)     // 114688
#define SMEM_TOTAL (B_OFF + 3 * B_BYTES)      // 212992 < 227KB

// Static scratch (allocation-free): bf16 copy of W only.
__device__ __nv_bfloat16 g_Wbf[(size_t)NEXP * HIDDEN];   // ~9.4 MB

#define NW4 ((NEXP * HIDDEN) / 4)

__global__ void __launch_bounds__(256)
convert_w_kernel(const float* __restrict__ srcW) {
    int i = blockIdx.x * blockDim.x + threadIdx.x;
    if (i < NW4) {
        float4 v = reinterpret_cast<const float4*>(srcW)[i];
        __nv_bfloat162 lo = __floats2bfloat162_rn(v.x, v.y);
        __nv_bfloat162 hi = __floats2bfloat162_rn(v.z, v.w);
        reinterpret_cast<__nv_bfloat162*>(g_Wbf)[2 * i]     = lo;
        reinterpret_cast<__nv_bfloat162*>(g_Wbf)[2 * i + 1] = hi;
    }
}

// ------------------------------- GEMM --------------------------------------
__device__ __forceinline__ uint32_t s2u(const void* p) {
    return (uint32_t)__cvta_generic_to_shared(p);
}

__device__ __forceinline__ void cp16(uint32_t s, const void* g) {
    asm volatile("cp.async.cg.shared.global [%0], [%1], 16;" :: "r"(s), "l"(g));
}

__device__ __forceinline__ uint32_t sw128(uint32_t o) {
    return o ^ ((o >> 3) & 0x70);
}

__device__ __forceinline__ void ldsm_x4(uint32_t& r0, uint32_t& r1,
                                        uint32_t& r2, uint32_t& r3, uint32_t addr) {
    asm volatile("ldmatrix.sync.aligned.m8n8.x4.shared.b16 {%0,%1,%2,%3}, [%4];"
                 : "=r"(r0), "=r"(r1), "=r"(r2), "=r"(r3) : "r"(addr));
}

__device__ __forceinline__ void mma16816(float* d, const uint32_t* a, const uint32_t* b) {
    asm volatile(
        "mma.sync.aligned.m16n8k16.row.col.f32.bf16.bf16.f32 "
        "{%0,%1,%2,%3}, {%4,%5,%6,%7}, {%8,%9}, {%0,%1,%2,%3};"
        : "+f"(d[0]), "+f"(d[1]), "+f"(d[2]), "+f"(d[3])
        : "r"(a[0]), "r"(a[1]), "r"(a[2]), "r"(a[3]), "r"(b[0]), "r"(b[1]));
}

// A stage loader: fp32, LINEAR smem layout. Chunk c of 2048 16B chunks:
//   row r = c>>4 (16 x 16B = 256B = KC floats per row), float col = (c&15)*4.
// K position comes from kbase ONLY (base pointer is always the tile origin).
__device__ __forceinline__ void load_stage_a32(const float* gA, uint32_t sA32,
                                               int tid, int kbase) {
    #pragma unroll
    for (int i = 0; i < (A32_BYTES / 16) / THREADS; i++) {    // 4 chunks
        int chunk = tid + i * THREADS;
        int row = chunk >> 4;
        int f = (chunk & 15) * 4;
        cp16(sA32 + (uint32_t)chunk * 16,
             gA + (size_t)row * HIDDEN + kbase + f);
    }
}

__device__ __forceinline__ void load_stage_b(const char* gB, uint32_t sB, int tid) {
    #pragma unroll
    for (int i = 0; i < (B_BYTES / 16) / THREADS; i++) {      // 4 chunks
        int chunk = tid + i * THREADS;
        int row = chunk >> 3;
        int c = (chunk & 7) * 16;
        cp16(sB + sw128((uint32_t)(row * 128 + c)), gB + (size_t)row * ROWB + c);
    }
}

// Thread-local convert: each thread reads back ITS OWN 4 fp32 chunks and
// writes the bf16 equivalents into the SW128 A tile (8B per chunk).
__device__ __forceinline__ void convert_a(char* smem, uint32_t a32_off,
                                          uint32_t abf_off, int tid) {
    #pragma unroll
    for (int i = 0; i < (A32_BYTES / 16) / THREADS; i++) {    // 4 chunks
        int chunk = tid + i * THREADS;
        int row = chunk >> 4;
        int f = (chunk & 15) * 4;                 // float index in row
        float4 v = *reinterpret_cast<const float4*>(smem + a32_off + chunk * 16);
        __nv_bfloat162 lo = __floats2bfloat162_rn(v.x, v.y);
        __nv_bfloat162 hi = __floats2bfloat162_rn(v.z, v.w);
        uint2 out = make_uint2(*reinterpret_cast<uint32_t*>(&lo),
                               *reinterpret_cast<uint32_t*>(&hi));
        // bf16 dest: row r, byte offset f*2 (8B aligned; sw128 preserves 8B)
        *reinterpret_cast<uint2*>(
            smem + abf_off + sw128((uint32_t)(row * 128 + f * 2))) = out;
    }
}

__global__ void __launch_bounds__(THREADS, 1)
router_gemm_kernel(const float* __restrict__ A, float* __restrict__ C) {
    extern __shared__ char smem[];
    const uint32_t sbase = s2u(smem);
    const int tid = threadIdx.x;
    const int wid = tid >> 5;
    const int lid = tid & 31;

    const int wm = wid & 3;        // warp row (0..3): 32 M-rows each
    const int wn = wid >> 2;       // warp col (0..3): 64 N-cols each

    const int n0 = blockIdx.x * TN;    // n-fast: 3 CTAs share the A tile in L2
    const int m0 = blockIdx.y * TM;

    const float* gA0 = A + (size_t)m0 * HIDDEN;
    const char* gB0 = (const char*)(g_Wbf + (size_t)n0 * HIDDEN);

    // Validated ldmatrix per-thread offsets.
    const int a_row = wm * 32 + (lid & 15);
    const int a_kb  = (lid >> 4) * 16;
    const int b_row = wn * 64 + (lid & 7) + ((lid >> 4) & 1) * 8;
    const int b_kb  = ((lid >> 3) & 1) * 16;

    float acc[2][8][4];
    #pragma unroll
    for (int mi = 0; mi < 2; mi++)
        #pragma unroll
        for (int ni = 0; ni < 8; ni++)
            #pragma unroll
            for (int j = 0; j < 4; j++) acc[mi][ni][j] = 0.0f;

    // Prologue: stages 0 and 1 in flight; convert stage 0.
    load_stage_a32(gA0, sbase + A32_OFF + 0 * A32_BYTES, tid, 0);
    load_stage_b(gB0, sbase + B_OFF + 0 * B_BYTES, tid);
    asm volatile("cp.async.commit_group;" ::: "memory");
    load_stage_a32(gA0, sbase + A32_OFF + 1 * A32_BYTES, tid, KC);
    load_stage_b(gB0 + KC * 2, sbase + B_OFF + 1 * B_BYTES, tid);
    asm volatile("cp.async.commit_group;" ::: "memory");

    asm volatile("cp.async.wait_group 1;" ::: "memory");   // stage 0 arrived
    convert_a(smem, A32_OFF + 0 * A32_BYTES, ABF_OFF + 0 * ABF_BYTES, tid);

    for (int kt = 0; kt < KT; kt++) {
        // 1) stage kt+1 arrived (exactly one group outstanding)
        if (kt + 1 < KT)
            asm volatile("cp.async.wait_group 0;" ::: "memory");

        // 2) convert stage kt+1 (thread-local chunks; pre-barrier legal)
        if (kt + 1 < KT)
            convert_a(smem, A32_OFF + ((kt + 1) & 1) * A32_BYTES,
                      ABF_OFF + ((kt + 1) % 3) * ABF_BYTES, tid);

        // 3) publish Abf[kt+1] (and B[kt+1]); guards all slot reuse
        __syncthreads();

        // 4) stage kt+2 loads (slots proven free after the sync)
        if (kt + 2 < KT) {
            load_stage_a32(gA0, sbase + A32_OFF + (kt & 1) * A32_BYTES, tid,
                           (kt + 2) * KC);     // FIXED: kbase only, base = gA0
            load_stage_b(gB0 + (size_t)(kt + 2) * (KC * 2),
                         sbase + B_OFF + ((kt + 2) % 3) * B_BYTES, tid);
            asm volatile("cp.async.commit_group;" ::: "memory");
        }

        // 5) compute stage kt (validated consumer, unchanged)
        const uint32_t sA = sbase + ABF_OFF + (kt % 3) * ABF_BYTES;
        const uint32_t sB = sbase + B_OFF + (kt % 3) * B_BYTES;

        #pragma unroll
        for (int ks = 0; ks < KC / 16; ks++) {
            uint32_t a[2][4];
            #pragma unroll
            for (int mi = 0; mi < 2; mi++) {
                uint32_t addr = sA + sw128((uint32_t)((a_row + mi * 16) * 128
                                                      + ks * 32 + a_kb));
                ldsm_x4(a[mi][0], a[mi][1], a[mi][2], a[mi][3], addr);
            }
            uint32_t b[8][2];
            #pragma unroll
            for (int ni2 = 0; ni2 < 4; ni2++) {
                uint32_t addr = sB + sw128((uint32_t)((b_row + ni2 * 16) * 128
                                                      + ks * 32 + b_kb));
                ldsm_x4(b[ni2 * 2][0], b[ni2 * 2][1],
                        b[ni2 * 2 + 1][0], b[ni2 * 2 + 1][1], addr);
            }
            #pragma unroll
            for (int mi = 0; mi < 2; mi++)
                #pragma unroll
                for (int ni = 0; ni < 8; ni++)
                    mma16816(acc[mi][ni], a[mi], b[ni]);
        }
    }

    // Epilogue: direct fp32 stores (validated layout).
    {
        const int tr = lid >> 2;
        const int tc = (lid & 3) * 2;
        #pragma unroll
        for (int mi = 0; mi < 2; mi++) {
            int row_lo = m0 + wm * 32 + mi * 16 + tr;
            float* out_lo = C + (size_t)row_lo * NEXP + n0 + wn * 64 + tc;
            float* out_hi = out_lo + 8 * NEXP;
            #pragma unroll
            for (int ni = 0; ni < 8; ni++) {
                *reinterpret_cast<float2*>(out_lo + ni * 8) =
                    make_float2(acc[mi][ni][0], acc[mi][ni][1]);
                *reinterpret_cast<float2*>(out_hi + ni * 8) =
                    make_float2(acc[mi][ni][2], acc[mi][ni][3]);
            }
        }
    }
}

extern "C" void kernel_launch(void* const* d_in, const int* in_sizes, int n_in,
                              void* d_out, int out_size) {
    const int nA = NTOK * HIDDEN;
    const float* Af;
    const float* Wf;
    if (in_sizes[0] == nA) {
        Af = (const float*)d_in[0];
        Wf = (const float*)d_in[1];
    } else {
        Af = (const float*)d_in[1];
        Wf = (const float*)d_in[0];
    }
    float* C = (float*)d_out;

    convert_w_kernel<<<(NW4 + 255) / 256, 256>>>(Wf);

    cudaFuncSetAttribute(router_gemm_kernel,
                         cudaFuncAttributeMaxDynamicSharedMemorySize, SMEM_TOTAL);
    dim3 grid(NEXP / TN, NTOK / TM);   // (3, 128)
    router_gemm_kernel<<<grid, THREADS, SMEM_TOTAL>>>(Af, C);
}